// round 14
// baseline (speedup 1.0000x reference)
#include <cuda_runtime.h>

#define BB 2
#define T 1024
#define C 1024
#define H 16
#define D 64
#define RM 32
#define NBIAS (2 * T - 1)

// ---------------- scratch (device globals; no allocation allowed) ----------------
__device__ float g_q[BB * H * T * D];
__device__ float g_k[BB * H * T * D];
__device__ float g_v[BB * H * T * D];
__device__ float g_y[BB * T * C];
__device__ float g_rc[T * RM];
__device__ float g_rs[T * RM];
__device__ float g_bias[BB * NBIAS];

// ---------------- fast exp (FMA pipe, avoids MUFU bottleneck) ----------------
__device__ __forceinline__ float fast_exp(float x) {
    x = fmaxf(x, -80.0f);
    float t = x * 1.442695040888963f;      // x * log2(e)
    float r = t + 12582912.0f;             // round-to-nearest-int trick
    float n = r - 12582912.0f;
    float f = t - n;
    float p = 1.3333558e-3f;
    p = fmaf(p, f, 9.6181291e-3f);
    p = fmaf(p, f, 5.5504109e-2f);
    p = fmaf(p, f, 2.4022650e-1f);
    p = fmaf(p, f, 6.9314718e-1f);
    p = fmaf(p, f, 1.0f);
    return __int_as_float(__float_as_int(p) + (((int)n) << 23));
}

// ---------------- table kernel: RoPE cos/sin + 1D Fourier bias table ----------------
__global__ void tables_kernel(const float* __restrict__ coords,
                              const float* __restrict__ W_rope,
                              const float* __restrict__ W_fb,
                              const float* __restrict__ bcos,
                              const float* __restrict__ bsin) {
    int idx = blockIdx.x * blockDim.x + threadIdx.x;
    if (idx < T * RM) {
        int t = idx / RM, m = idx % RM;
        float th = coords[t] * W_rope[m];
        float s, c;
        sincosf(th, &s, &c);
        g_rc[idx] = c;
        g_rs[idx] = s;
    } else {
        int j = idx - T * RM;
        if (j < BB * NBIAS) {
            int b = j / NBIAS;
            int d = j % NBIAS - (T - 1);
            int q = d > 0 ? d : 0;
            int k = d > 0 ? 0 : -d;
            float delta = coords[b * T + q] - coords[b * T + k];
            float acc = 0.f;
            #pragma unroll 8
            for (int m = 0; m < 32; m++) {
                float s, c;
                sincosf(delta * W_fb[m], &s, &c);
                acc = fmaf(c, bcos[m], acc);
                acc = fmaf(s, bsin[m], acc);
            }
            g_bias[j] = acc * 0.17677669529663687f;  // 1/sqrt(FB_M)
        }
    }
}

// ---------------- SGEMM tiles: 64x128, per-thread 4x8 ----------------
// Retiled from 128x128 (R6 profile: occ=12.5%, ONE CTA/SM, issue=59%).
// 64x128 tiles double/triple the grid and cut regs to ~75 so ~3 CTAs
// co-reside per SM -> latency hidden, fma pipe toward saturation.
#define BM 64
#define BN 128
#define BK 16

#define TILE_STORE(buf)                                                            \
    As[buf][lc + 0][lr] = a0.x; As[buf][lc + 1][lr] = a0.y;                        \
    As[buf][lc + 2][lr] = a0.z; As[buf][lc + 3][lr] = a0.w;                        \
    Bs[buf][lc + 0][lr] = b0.x; Bs[buf][lc + 1][lr] = b0.y;                        \
    Bs[buf][lc + 2][lr] = b0.z; Bs[buf][lc + 3][lr] = b0.w;                        \
    Bs[buf][lc + 0][lr + 64] = b1.x; Bs[buf][lc + 1][lr + 64] = b1.y;              \
    Bs[buf][lc + 2][lr + 64] = b1.z; Bs[buf][lc + 3][lr + 64] = b1.w;

#define GEMM_MAIN_LOOP(AGP, BGP, KDIM)                                             \
    float acc[4][8];                                                               \
    _Pragma("unroll") for (int i = 0; i < 4; i++)                                  \
        _Pragma("unroll") for (int j = 0; j < 8; j++) acc[i][j] = 0.f;             \
    __syncthreads();                                                               \
    const int NK = (KDIM) / BK;                                                    \
    for (int kt = 0; kt < NK; kt++) {                                              \
        int cur = kt & 1;                                                          \
        if (kt + 1 < NK) {                                                         \
            const float* Ap = (AGP) + (kt + 1) * BK;                               \
            const float* Bp = (BGP) + (kt + 1) * BK;                               \
            a0 = *(const float4*)(Ap);                                             \
            b0 = *(const float4*)(Bp);                                             \
            b1 = *(const float4*)(Bp + 64 * (KDIM));                               \
        }                                                                          \
        _Pragma("unroll") for (int k = 0; k < BK; k++) {                           \
            float4 ra0 = *(const float4*)(&As[cur][k][4 * ty]);                    \
            float4 rb0 = *(const float4*)(&Bs[cur][k][4 * tx]);                    \
            float4 rb1 = *(const float4*)(&Bs[cur][k][4 * tx + 64]);               \
            float av[4] = {ra0.x, ra0.y, ra0.z, ra0.w};                            \
            float bv[8] = {rb0.x, rb0.y, rb0.z, rb0.w, rb1.x, rb1.y, rb1.z, rb1.w};\
            _Pragma("unroll") for (int i = 0; i < 4; i++)                          \
                _Pragma("unroll") for (int j = 0; j < 8; j++)                      \
                    acc[i][j] = fmaf(av[i], bv[j], acc[i][j]);                     \
        }                                                                          \
        if (kt + 1 < NK) { int nxt = cur ^ 1; TILE_STORE(nxt); }                   \
        __syncthreads();                                                           \
    }

// QKV GEMM: qkv = x @ W_attn^T + b_attn, fused RoPE (q,k), 1/sqrt(D) into q,
// scatter to [B][H][T][D].
__global__ __launch_bounds__(256, 2)
void qkv_kernel(const float* __restrict__ A,      // x [2048,1024]
                const float* __restrict__ W,      // W_attn [3072,1024]
                const float* __restrict__ bvec) { // b_attn [3072]
    __shared__ float As[2][BK][BM];
    __shared__ float Bs[2][BK][BN];
    const int K = C;
    int tid = threadIdx.x;
    int m0 = blockIdx.y * BM;
    int n0 = blockIdx.x * BN;
    int lr = tid >> 2;           // 0..63
    int lc = (tid & 3) << 2;     // 0,4,8,12
    int tx = tid & 15;
    int ty = tid >> 4;

    const float* Ag = A + (m0 + lr) * K + lc;
    const float* Wg = W + (n0 + lr) * K + lc;

    float4 a0 = *(const float4*)(Ag);
    float4 b0 = *(const float4*)(Wg);
    float4 b1 = *(const float4*)(Wg + 64 * K);
    TILE_STORE(0);

    GEMM_MAIN_LOOP(Ag, Wg, K);

    #pragma unroll
    for (int i = 0; i < 4; i++) {
        int m = m0 + 4 * ty + i;
        int bidx = m >> 10;
        int t = m & 1023;
        #pragma unroll
        for (int g = 0; g < 2; g++) {
            int n = n0 + 4 * tx + g * 64;
            float v0 = acc[i][4 * g + 0] + bvec[n + 0];
            float v1 = acc[i][4 * g + 1] + bvec[n + 1];
            float v2 = acc[i][4 * g + 2] + bvec[n + 2];
            float v3 = acc[i][4 * g + 3] + bvec[n + 3];
            int sec = n >> 10;
            int cin = n & 1023;
            int h = cin >> 6;
            int d0 = cin & 63;
            int base = ((bidx * H + h) * T + t) * D + d0;
            if (sec == 2) {
                g_v[base + 0] = v0; g_v[base + 1] = v1;
                g_v[base + 2] = v2; g_v[base + 3] = v3;
            } else {
                int mi = d0 >> 1;
                float c0 = g_rc[t * RM + mi],     s0 = g_rs[t * RM + mi];
                float c1 = g_rc[t * RM + mi + 1], s1 = g_rs[t * RM + mi + 1];
                float y0 = v0 * c0 - v1 * s0;
                float y1 = v0 * s0 + v1 * c0;
                float y2 = v2 * c1 - v3 * s1;
                float y3 = v2 * s1 + v3 * c1;
                float sc = (sec == 0) ? 0.125f : 1.0f;  // fold 1/sqrt(D) into q
                float* dst = (sec == 0) ? g_q : g_k;
                dst[base + 0] = y0 * sc; dst[base + 1] = y1 * sc;
                dst[base + 2] = y2 * sc; dst[base + 3] = y3 * sc;
            }
        }
    }
}

// proj GEMM: out = x + g_y @ W_proj^T + b_proj
__global__ __launch_bounds__(256, 2)
void proj_kernel(const float* __restrict__ X,     // x [2048,1024] (residual)
                 const float* __restrict__ W,     // W_proj [1024,1024]
                 const float* __restrict__ bvec,  // b_proj
                 float* __restrict__ out) {
    __shared__ float As[2][BK][BM];
    __shared__ float Bs[2][BK][BN];
    const int K = C;
    int tid = threadIdx.x;
    int m0 = blockIdx.y * BM;
    int n0 = blockIdx.x * BN;
    int lr = tid >> 2;
    int lc = (tid & 3) << 2;
    int tx = tid & 15;
    int ty = tid >> 4;

    const float* Ag = g_y + (m0 + lr) * K + lc;
    const float* Wg = W + (n0 + lr) * K + lc;

    float4 a0 = *(const float4*)(Ag);
    float4 b0 = *(const float4*)(Wg);
    float4 b1 = *(const float4*)(Wg + 64 * K);
    TILE_STORE(0);

    GEMM_MAIN_LOOP(Ag, Wg, K);

    #pragma unroll
    for (int i = 0; i < 4; i++) {
        int m = m0 + 4 * ty + i;
        #pragma unroll
        for (int g = 0; g < 2; g++) {
            int n = n0 + 4 * tx + g * 64;
            float4 xr = *(const float4*)(X + m * C + n);
            float4 r;
            r.x = acc[i][4 * g + 0] + bvec[n + 0] + xr.x;
            r.y = acc[i][4 * g + 1] + bvec[n + 1] + xr.y;
            r.z = acc[i][4 * g + 2] + bvec[n + 2] + xr.z;
            r.w = acc[i][4 * g + 3] + bvec[n + 3] + xr.w;
            *(float4*)(out + m * C + n) = r;
        }
    }
}

// ---------------- flash attention (fp32 SIMT, online softmax) ----------------
// Smem: Q, K, V tiles of 64x64 (padded LDP=65) + 127-entry bias slice.
// P aliases the K tile (K dead after the QK^T loop); barrier-separated.
#define LDP 65
#define ATTN_SMEM ((3 * 64 * LDP + 128) * (int)sizeof(float))

__global__ __launch_bounds__(128)
void attn_kernel() {
    extern __shared__ float smf[];
    float* Qs = smf;
    float* Ks = Qs + 64 * LDP;
    float* Vs = Ks + 64 * LDP;
    float* Ps = Ks;                 // alias: K tile reused for P after scores
    float* sb = Vs + 64 * LDP;

    int tid = threadIdx.x;
    int tx = tid & 15;
    int ty = tid >> 4;
    int b = blockIdx.z;
    int h = blockIdx.y;
    int q0 = blockIdx.x * 64;

    const float* Qg = g_q + ((b * H + h) * T + q0) * D;
    const float* Kg = g_k + ((b * H + h) * T) * D;
    const float* Vg = g_v + ((b * H + h) * T) * D;
    const float* bias_b = g_bias + b * NBIAS + (T - 1) + q0 - 63;

    for (int i = tid; i < 1024; i += 128) {
        int row = i >> 4;
        int c4 = (i & 15) << 2;
        float4 v = *(const float4*)(Qg + row * D + c4);
        float* dst = Qs + row * LDP + c4;
        dst[0] = v.x; dst[1] = v.y; dst[2] = v.z; dst[3] = v.w;
    }

    float mrow[8], lrow[8], o[8][4];
    #pragma unroll
    for (int i = 0; i < 8; i++) {
        mrow[i] = -1e30f;
        lrow[i] = 0.f;
        o[i][0] = o[i][1] = o[i][2] = o[i][3] = 0.f;
    }

    for (int kt = 0; kt < T / 64; kt++) {
        int k0 = kt * 64;
        __syncthreads();            // prev iter's P/V readers done before overwrite
        for (int i = tid; i < 1024; i += 128) {
            int row = i >> 4;
            int c4 = (i & 15) << 2;
            float4 kv = *(const float4*)(Kg + (k0 + row) * D + c4);
            float* dk = Ks + row * LDP + c4;
            dk[0] = kv.x; dk[1] = kv.y; dk[2] = kv.z; dk[3] = kv.w;
            float4 vv = *(const float4*)(Vg + (k0 + row) * D + c4);
            float* dv = Vs + row * LDP + c4;
            dv[0] = vv.x; dv[1] = vv.y; dv[2] = vv.z; dv[3] = vv.w;
        }
        if (tid < 127) sb[tid] = bias_b[tid - k0];
        __syncthreads();

        float s[8][4];
        #pragma unroll
        for (int i = 0; i < 8; i++)
            s[i][0] = s[i][1] = s[i][2] = s[i][3] = 0.f;

        #pragma unroll 8
        for (int d = 0; d < 64; d++) {
            float kv0 = Ks[(tx) * LDP + d];
            float kv1 = Ks[(tx + 16) * LDP + d];
            float kv2 = Ks[(tx + 32) * LDP + d];
            float kv3 = Ks[(tx + 48) * LDP + d];
            #pragma unroll
            for (int i = 0; i < 8; i++) {
                float qv = Qs[(ty + 8 * i) * LDP + d];
                s[i][0] = fmaf(qv, kv0, s[i][0]);
                s[i][1] = fmaf(qv, kv1, s[i][1]);
                s[i][2] = fmaf(qv, kv2, s[i][2]);
                s[i][3] = fmaf(qv, kv3, s[i][3]);
            }
        }

        #pragma unroll
        for (int i = 0; i < 8; i++) {
            int ri = ty + 8 * i;
            float p0 = s[i][0] + sb[ri - tx + 63];
            float p1 = s[i][1] + sb[ri - tx + 47];
            float p2 = s[i][2] + sb[ri - tx + 31];
            float p3 = s[i][3] + sb[ri - tx + 15];
            float rmax = fmaxf(fmaxf(p0, p1), fmaxf(p2, p3));
            rmax = fmaxf(rmax, __shfl_xor_sync(0xffffffffu, rmax, 1));
            rmax = fmaxf(rmax, __shfl_xor_sync(0xffffffffu, rmax, 2));
            rmax = fmaxf(rmax, __shfl_xor_sync(0xffffffffu, rmax, 4));
            rmax = fmaxf(rmax, __shfl_xor_sync(0xffffffffu, rmax, 8));
            float nm = fmaxf(mrow[i], rmax);
            p0 = fast_exp(p0 - nm);
            p1 = fast_exp(p1 - nm);
            p2 = fast_exp(p2 - nm);
            p3 = fast_exp(p3 - nm);
            float rs = p0 + p1 + p2 + p3;
            rs += __shfl_xor_sync(0xffffffffu, rs, 1);
            rs += __shfl_xor_sync(0xffffffffu, rs, 2);
            rs += __shfl_xor_sync(0xffffffffu, rs, 4);
            rs += __shfl_xor_sync(0xffffffffu, rs, 8);
            float corr = fast_exp(mrow[i] - nm);
            mrow[i] = nm;
            lrow[i] = fmaf(lrow[i], corr, rs);
            o[i][0] *= corr; o[i][1] *= corr; o[i][2] *= corr; o[i][3] *= corr;
            s[i][0] = p0; s[i][1] = p1; s[i][2] = p2; s[i][3] = p3;
        }
        __syncthreads();            // all warps finished reading Ks
        #pragma unroll
        for (int i = 0; i < 8; i++) {
            int ri = ty + 8 * i;
            Ps[ri * LDP + tx]      = s[i][0];
            Ps[ri * LDP + tx + 16] = s[i][1];
            Ps[ri * LDP + tx + 32] = s[i][2];
            Ps[ri * LDP + tx + 48] = s[i][3];
        }
        __syncthreads();            // P visible to all warps

        #pragma unroll 8
        for (int kc = 0; kc < 64; kc++) {
            float v0 = Vs[kc * LDP + tx];
            float v1 = Vs[kc * LDP + tx + 16];
            float v2 = Vs[kc * LDP + tx + 32];
            float v3 = Vs[kc * LDP + tx + 48];
            #pragma unroll
            for (int i = 0; i < 8; i++) {
                float pv = Ps[(ty + 8 * i) * LDP + kc];
                o[i][0] = fmaf(pv, v0, o[i][0]);
                o[i][1] = fmaf(pv, v1, o[i][1]);
                o[i][2] = fmaf(pv, v2, o[i][2]);
                o[i][3] = fmaf(pv, v3, o[i][3]);
            }
        }
    }

    #pragma unroll
    for (int i = 0; i < 8; i++) {
        float inv = 1.0f / lrow[i];
        int t = q0 + ty + 8 * i;
        float* dst = g_y + (b * T + t) * C + h * D + tx;
        dst[0]  = o[i][0] * inv;
        dst[16] = o[i][1] * inv;
        dst[32] = o[i][2] * inv;
        dst[48] = o[i][3] * inv;
    }
}

// ---------------- launch ----------------
extern "C" void kernel_launch(void* const* d_in, const int* in_sizes, int n_in,
                              void* d_out, int out_size) {
    const float* x      = (const float*)d_in[0];
    const float* coords = (const float*)d_in[1];
    const float* W_attn = (const float*)d_in[2];
    const float* b_attn = (const float*)d_in[3];
    const float* W_proj = (const float*)d_in[4];
    const float* b_proj = (const float*)d_in[5];
    const float* W_rope = (const float*)d_in[6];
    const float* W_fb   = (const float*)d_in[7];
    const float* bcos   = (const float*)d_in[8];
    const float* bsin   = (const float*)d_in[9];
    float* out = (float*)d_out;

    cudaFuncSetAttribute(attn_kernel,
                         cudaFuncAttributeMaxDynamicSharedMemorySize, ATTN_SMEM);

    int tbl_threads = T * RM + BB * NBIAS;
    tables_kernel<<<(tbl_threads + 255) / 256, 256>>>(coords, W_rope, W_fb, bcos, bsin);
    qkv_kernel<<<dim3(3 * C / BN, BB * T / BM), 256>>>(x, W_attn, b_attn);
    attn_kernel<<<dim3(T / 64, H, BB), 128, ATTN_SMEM>>>();
    proj_kernel<<<dim3(C / BN, BB * T / BM), 256>>>(x, W_proj, b_proj, out);
}

// round 17
// speedup vs baseline: 1.3325x; 1.3325x over previous
#include <cuda_runtime.h>
#include <cstdint>

#define BB 2
#define T 1024
#define C 1024
#define H 16
#define D 64
#define RM 32
#define NBIAS (2 * T - 1)
#define GK 1024
#define NSTG 32

// ---------------- scratch (device globals; no allocation allowed) ----------------
__device__ float g_q[BB * H * T * D];
__device__ float g_k[BB * H * T * D];
__device__ float g_v[BB * H * T * D];
__device__ float g_y[BB * T * C];
__device__ float g_rc[T * RM];
__device__ float g_rs[T * RM];
__device__ float g_bias[BB * NBIAS];

// ---------------- helpers ----------------
__device__ __forceinline__ float fast_exp(float x) {
    x = fmaxf(x, -80.0f);
    float t = x * 1.442695040888963f;
    float r = t + 12582912.0f;
    float n = r - 12582912.0f;
    float f = t - n;
    float p = 1.3333558e-3f;
    p = fmaf(p, f, 9.6181291e-3f);
    p = fmaf(p, f, 5.5504109e-2f);
    p = fmaf(p, f, 2.4022650e-1f);
    p = fmaf(p, f, 6.9314718e-1f);
    p = fmaf(p, f, 1.0f);
    return __int_as_float(__float_as_int(p) + (((int)n) << 23));
}

// pack two f32 -> bf16x2; low half = first arg (= lower k index)
__device__ __forceinline__ uint32_t pack_bf2(float a, float b) {
    uint32_t r;
    asm("cvt.rn.satfinite.bf16x2.f32 %0, %1, %2;" : "=r"(r) : "f"(b), "f"(a));
    return r;
}
__device__ __forceinline__ float lo_f(uint32_t u) { return __uint_as_float(u << 16); }
__device__ __forceinline__ float hi_f(uint32_t u) { return __uint_as_float(u & 0xFFFF0000u); }

// kp swizzle (kp in [0,16)); verified 2-way (minimal) for both the
// 8-rows-per-warp store pattern and the g/t fragment load pattern.
__device__ __forceinline__ int swz(int row, int kp) {
    return kp ^ ((row & 3) << 2) ^ ((row >> 2) & 3);
}

// m16n8k16 bf16 mma, fp32 accum (baseline PTX sm_80+, compiles to HMMA on sm_103)
#define MMA_BF16(d, a, b)                                                         \
    asm volatile(                                                                 \
        "mma.sync.aligned.m16n8k16.row.col.f32.bf16.bf16.f32 "                    \
        "{%0,%1,%2,%3}, {%4,%5,%6,%7}, {%8,%9}, {%0,%1,%2,%3};"                   \
        : "+f"((d)[0]), "+f"((d)[1]), "+f"((d)[2]), "+f"((d)[3])                  \
        : "r"((a)[0]), "r"((a)[1]), "r"((a)[2]), "r"((a)[3]),                     \
          "r"((b)[0]), "r"((b)[1]))

// ---------------- tables ----------------
__global__ void tables_kernel(const float* __restrict__ coords,
                              const float* __restrict__ W_rope,
                              const float* __restrict__ W_fb,
                              const float* __restrict__ bcos,
                              const float* __restrict__ bsin) {
    int idx = blockIdx.x * blockDim.x + threadIdx.x;
    if (idx < T * RM) {
        int t = idx / RM, m = idx % RM;
        float th = coords[t] * W_rope[m];
        float s, c;
        sincosf(th, &s, &c);
        g_rc[idx] = c;
        g_rs[idx] = s;
    } else {
        int j = idx - T * RM;
        if (j < BB * NBIAS) {
            int b = j / NBIAS;
            int d = j % NBIAS - (T - 1);
            int q = d > 0 ? d : 0;
            int k = d > 0 ? 0 : -d;
            float delta = coords[b * T + q] - coords[b * T + k];
            float acc = 0.f;
            #pragma unroll 8
            for (int m = 0; m < 32; m++) {
                float s, c;
                sincosf(delta * W_fb[m], &s, &c);
                acc = fmaf(c, bcos[m], acc);
                acc = fmaf(s, bsin[m], acc);
            }
            g_bias[j] = acc * 0.17677669529663687f;
        }
    }
}

// ---------------- split-bf16 tensor-core GEMM (mma.sync) ----------------
// CTA tile 64x128, 128 threads = 4 warps in 2(M)x2(N) grid, warp tile 32x64.
// K in 32-wide stages, double-buffered smem of (hi,lo) bf16x2 uint2 pairs.
// 3-term split: D = Ah*Bh + Ah*Bl + Al*Bh (rel err ~2^-18, fp32 accum).
#define GEMM_SMEM (6144 * (int)sizeof(uint2))  // (1024 + 2048) uint2 x 2 stages = 48KB

template <int EPI>
__global__ __launch_bounds__(128, 3) void gemm_mma(
    const float* __restrict__ A,     // EPI=0: x ; EPI=1: unused (g_y)
    const float* __restrict__ Bw,    // weights [N, 1024] (K-major)
    const float* __restrict__ bvec,  // bias [N]
    const float* __restrict__ X,     // residual (EPI=1)
    float* __restrict__ out)         // output (EPI=1)
{
    extern __shared__ uint2 smem2[];
    uint2* As = smem2;          // [2][64*16]
    uint2* Bs = smem2 + 2048;   // [2][128*16]

    int tid = threadIdx.x;
    int lane = tid & 31, wid = tid >> 5;
    int wm = wid & 1, wn = wid >> 1;
    int g = lane >> 2, t = lane & 3;
    int m0 = blockIdx.y * 64, n0 = blockIdx.x * 128;

    const float* Ap = (EPI == 0) ? A : (const float*)g_y;

    // loader mapping: 8 consecutive 8-aligned rows per warp -> 2-way STS banks
    int ar = tid >> 2;        // 0..31
    int af = tid & 3;         // 0..3

    float acc[2][8][4];
    #pragma unroll
    for (int a = 0; a < 2; a++)
        #pragma unroll
        for (int b = 0; b < 8; b++)
            #pragma unroll
            for (int c = 0; c < 4; c++) acc[a][b][c] = 0.f;

    float4 pfA[4], pfB[8];

    #define LOAD_STAGE(S)                                                          \
        _Pragma("unroll") for (int r = 0; r < 4; r++) {                            \
            int row = ar + (r >> 1) * 32, f = af + (r & 1) * 4;                    \
            pfA[r] = *(const float4*)(Ap + (size_t)(m0 + row) * GK + (S) * 32 + f * 4); \
        }                                                                          \
        _Pragma("unroll") for (int r = 0; r < 8; r++) {                            \
            int row = ar + (r >> 1) * 32, f = af + (r & 1) * 4;                    \
            pfB[r] = *(const float4*)(Bw + (size_t)(n0 + row) * GK + (S) * 32 + f * 4); \
        }

    #define STORE_ONE(ARR, OFF, ROW, F, V)                                         \
        {                                                                          \
            uint32_t h01 = pack_bf2((V).x, (V).y);                                 \
            uint32_t l01 = pack_bf2((V).x - lo_f(h01), (V).y - hi_f(h01));         \
            uint32_t h23 = pack_bf2((V).z, (V).w);                                 \
            uint32_t l23 = pack_bf2((V).z - lo_f(h23), (V).w - hi_f(h23));         \
            (ARR)[(OFF) + (ROW) * 16 + swz((ROW), 2 * (F))]     = make_uint2(h01, l01); \
            (ARR)[(OFF) + (ROW) * 16 + swz((ROW), 2 * (F) + 1)] = make_uint2(h23, l23); \
        }

    #define STORE_STAGE(BUF)                                                       \
        _Pragma("unroll") for (int r = 0; r < 4; r++) {                            \
            int row = ar + (r >> 1) * 32, f = af + (r & 1) * 4;                    \
            STORE_ONE(As, (BUF) * 1024, row, f, pfA[r]);                           \
        }                                                                          \
        _Pragma("unroll") for (int r = 0; r < 8; r++) {                            \
            int row = ar + (r >> 1) * 32, f = af + (r & 1) * 4;                    \
            STORE_ONE(Bs, (BUF) * 2048, row, f, pfB[r]);                           \
        }

    LOAD_STAGE(0);
    STORE_STAGE(0);
    __syncthreads();

    for (int s = 0; s < NSTG; s++) {
        int cur = s & 1;
        if (s + 1 < NSTG) { LOAD_STAGE(s + 1); }

        #pragma unroll
        for (int j = 0; j < 2; j++) {
            uint32_t bh[8][2], bl[8][2];
            #pragma unroll
            for (int nb = 0; nb < 8; nb++) {
                int rowB = wn * 64 + nb * 8 + g;
                uint2 v0 = Bs[cur * 2048 + rowB * 16 + swz(rowB, j * 8 + t)];
                uint2 v1 = Bs[cur * 2048 + rowB * 16 + swz(rowB, j * 8 + 4 + t)];
                bh[nb][0] = v0.x; bl[nb][0] = v0.y;
                bh[nb][1] = v1.x; bl[nb][1] = v1.y;
            }
            #pragma unroll
            for (int mb = 0; mb < 2; mb++) {
                int rowA = wm * 32 + mb * 16 + g;
                uint2 u0 = As[cur * 1024 + rowA * 16       + swz(rowA,     j * 8 + t)];
                uint2 u1 = As[cur * 1024 + (rowA + 8) * 16 + swz(rowA + 8, j * 8 + t)];
                uint2 u2 = As[cur * 1024 + rowA * 16       + swz(rowA,     j * 8 + 4 + t)];
                uint2 u3 = As[cur * 1024 + (rowA + 8) * 16 + swz(rowA + 8, j * 8 + 4 + t)];
                uint32_t ah[4] = {u0.x, u1.x, u2.x, u3.x};
                uint32_t al[4] = {u0.y, u1.y, u2.y, u3.y};
                #pragma unroll
                for (int nb = 0; nb < 8; nb++) {
                    MMA_BF16(acc[mb][nb], ah, bh[nb]);
                    MMA_BF16(acc[mb][nb], ah, bl[nb]);
                    MMA_BF16(acc[mb][nb], al, bh[nb]);
                }
            }
        }

        if (s + 1 < NSTG) { STORE_STAGE(cur ^ 1); }
        __syncthreads();
    }

    // ---------------- epilogue ----------------
    #pragma unroll
    for (int mb = 0; mb < 2; mb++) {
        #pragma unroll
        for (int nb = 0; nb < 8; nb++) {
            int n = n0 + wn * 64 + nb * 8 + 2 * t;
            #pragma unroll
            for (int half = 0; half < 2; half++) {
                int row = m0 + wm * 32 + mb * 16 + g + half * 8;
                float v0 = acc[mb][nb][2 * half + 0] + bvec[n];
                float v1 = acc[mb][nb][2 * half + 1] + bvec[n + 1];
                if (EPI == 0) {
                    int bidx = row >> 10, tt = row & 1023;
                    int sec = n >> 10, cin = n & 1023;
                    int hh = cin >> 6, d0 = cin & 63;
                    size_t base = ((size_t)(bidx * H + hh) * T + tt) * D + d0;
                    if (sec == 2) {
                        *(float2*)(g_v + base) = make_float2(v0, v1);
                    } else {
                        int mi = d0 >> 1;
                        float cc = g_rc[tt * RM + mi], ss = g_rs[tt * RM + mi];
                        float y0 = v0 * cc - v1 * ss;
                        float y1 = v0 * ss + v1 * cc;
                        float sc = (sec == 0) ? 0.125f : 1.0f;
                        float* dst = ((sec == 0) ? g_q : g_k) + base;
                        *(float2*)dst = make_float2(y0 * sc, y1 * sc);
                    }
                } else {
                    float2 xr = *(const float2*)(X + (size_t)row * C + n);
                    *(float2*)(out + (size_t)row * C + n) =
                        make_float2(v0 + xr.x, v1 + xr.y);
                }
            }
        }
    }
}

// ---------------- flash attention (fp32 SIMT, online softmax) ----------------
#define LDP 65
#define ATTN_SMEM ((3 * 64 * LDP + 128) * (int)sizeof(float))

__global__ __launch_bounds__(128)
void attn_kernel() {
    extern __shared__ float smf[];
    float* Qs = smf;
    float* Ks = Qs + 64 * LDP;
    float* Vs = Ks + 64 * LDP;
    float* Ps = Ks;                 // alias: K tile reused for P after scores
    float* sb = Vs + 64 * LDP;

    int tid = threadIdx.x;
    int tx = tid & 15;
    int ty = tid >> 4;
    int b = blockIdx.z;
    int h = blockIdx.y;
    int q0 = blockIdx.x * 64;

    const float* Qg = g_q + ((b * H + h) * T + q0) * D;
    const float* Kg = g_k + ((b * H + h) * T) * D;
    const float* Vg = g_v + ((b * H + h) * T) * D;
    const float* bias_b = g_bias + b * NBIAS + (T - 1) + q0 - 63;

    for (int i = tid; i < 1024; i += 128) {
        int row = i >> 4;
        int c4 = (i & 15) << 2;
        float4 v = *(const float4*)(Qg + row * D + c4);
        float* dst = Qs + row * LDP + c4;
        dst[0] = v.x; dst[1] = v.y; dst[2] = v.z; dst[3] = v.w;
    }

    float mrow[8], lrow[8], o[8][4];
    #pragma unroll
    for (int i = 0; i < 8; i++) {
        mrow[i] = -1e30f;
        lrow[i] = 0.f;
        o[i][0] = o[i][1] = o[i][2] = o[i][3] = 0.f;
    }

    for (int kt = 0; kt < T / 64; kt++) {
        int k0 = kt * 64;
        __syncthreads();
        for (int i = tid; i < 1024; i += 128) {
            int row = i >> 4;
            int c4 = (i & 15) << 2;
            float4 kv = *(const float4*)(Kg + (k0 + row) * D + c4);
            float* dk = Ks + row * LDP + c4;
            dk[0] = kv.x; dk[1] = kv.y; dk[2] = kv.z; dk[3] = kv.w;
            float4 vv = *(const float4*)(Vg + (k0 + row) * D + c4);
            float* dv = Vs + row * LDP + c4;
            dv[0] = vv.x; dv[1] = vv.y; dv[2] = vv.z; dv[3] = vv.w;
        }
        if (tid < 127) sb[tid] = bias_b[tid - k0];
        __syncthreads();

        float s[8][4];
        #pragma unroll
        for (int i = 0; i < 8; i++)
            s[i][0] = s[i][1] = s[i][2] = s[i][3] = 0.f;

        #pragma unroll 8
        for (int d = 0; d < 64; d++) {
            float kv0 = Ks[(tx) * LDP + d];
            float kv1 = Ks[(tx + 16) * LDP + d];
            float kv2 = Ks[(tx + 32) * LDP + d];
            float kv3 = Ks[(tx + 48) * LDP + d];
            #pragma unroll
            for (int i = 0; i < 8; i++) {
                float qv = Qs[(ty + 8 * i) * LDP + d];
                s[i][0] = fmaf(qv, kv0, s[i][0]);
                s[i][1] = fmaf(qv, kv1, s[i][1]);
                s[i][2] = fmaf(qv, kv2, s[i][2]);
                s[i][3] = fmaf(qv, kv3, s[i][3]);
            }
        }

        #pragma unroll
        for (int i = 0; i < 8; i++) {
            int ri = ty + 8 * i;
            float p0 = s[i][0] + sb[ri - tx + 63];
            float p1 = s[i][1] + sb[ri - tx + 47];
            float p2 = s[i][2] + sb[ri - tx + 31];
            float p3 = s[i][3] + sb[ri - tx + 15];
            float rmax = fmaxf(fmaxf(p0, p1), fmaxf(p2, p3));
            rmax = fmaxf(rmax, __shfl_xor_sync(0xffffffffu, rmax, 1));
            rmax = fmaxf(rmax, __shfl_xor_sync(0xffffffffu, rmax, 2));
            rmax = fmaxf(rmax, __shfl_xor_sync(0xffffffffu, rmax, 4));
            rmax = fmaxf(rmax, __shfl_xor_sync(0xffffffffu, rmax, 8));
            float nm = fmaxf(mrow[i], rmax);
            p0 = fast_exp(p0 - nm);
            p1 = fast_exp(p1 - nm);
            p2 = fast_exp(p2 - nm);
            p3 = fast_exp(p3 - nm);
            float rs = p0 + p1 + p2 + p3;
            rs += __shfl_xor_sync(0xffffffffu, rs, 1);
            rs += __shfl_xor_sync(0xffffffffu, rs, 2);
            rs += __shfl_xor_sync(0xffffffffu, rs, 4);
            rs += __shfl_xor_sync(0xffffffffu, rs, 8);
            float corr = fast_exp(mrow[i] - nm);
            mrow[i] = nm;
            lrow[i] = fmaf(lrow[i], corr, rs);
            o[i][0] *= corr; o[i][1] *= corr; o[i][2] *= corr; o[i][3] *= corr;
            s[i][0] = p0; s[i][1] = p1; s[i][2] = p2; s[i][3] = p3;
        }
        __syncthreads();
        #pragma unroll
        for (int i = 0; i < 8; i++) {
            int ri = ty + 8 * i;
            Ps[ri * LDP + tx]      = s[i][0];
            Ps[ri * LDP + tx + 16] = s[i][1];
            Ps[ri * LDP + tx + 32] = s[i][2];
            Ps[ri * LDP + tx + 48] = s[i][3];
        }
        __syncthreads();

        #pragma unroll 8
        for (int kc = 0; kc < 64; kc++) {
            float v0 = Vs[kc * LDP + tx];
            float v1 = Vs[kc * LDP + tx + 16];
            float v2 = Vs[kc * LDP + tx + 32];
            float v3 = Vs[kc * LDP + tx + 48];
            #pragma unroll
            for (int i = 0; i < 8; i++) {
                float pv = Ps[(ty + 8 * i) * LDP + kc];
                o[i][0] = fmaf(pv, v0, o[i][0]);
                o[i][1] = fmaf(pv, v1, o[i][1]);
                o[i][2] = fmaf(pv, v2, o[i][2]);
                o[i][3] = fmaf(pv, v3, o[i][3]);
            }
        }
    }

    #pragma unroll
    for (int i = 0; i < 8; i++) {
        float inv = 1.0f / lrow[i];
        int t = q0 + ty + 8 * i;
        float* dst = g_y + (b * T + t) * C + h * D + tx;
        dst[0]  = o[i][0] * inv;
        dst[16] = o[i][1] * inv;
        dst[32] = o[i][2] * inv;
        dst[48] = o[i][3] * inv;
    }
}

// ---------------- launch ----------------
extern "C" void kernel_launch(void* const* d_in, const int* in_sizes, int n_in,
                              void* d_out, int out_size) {
    const float* x      = (const float*)d_in[0];
    const float* coords = (const float*)d_in[1];
    const float* W_attn = (const float*)d_in[2];
    const float* b_attn = (const float*)d_in[3];
    const float* W_proj = (const float*)d_in[4];
    const float* b_proj = (const float*)d_in[5];
    const float* W_rope = (const float*)d_in[6];
    const float* W_fb   = (const float*)d_in[7];
    const float* bcos   = (const float*)d_in[8];
    const float* bsin   = (const float*)d_in[9];
    float* out = (float*)d_out;

    cudaFuncSetAttribute(attn_kernel,
                         cudaFuncAttributeMaxDynamicSharedMemorySize, ATTN_SMEM);
    cudaFuncSetAttribute(gemm_mma<0>,
                         cudaFuncAttributeMaxDynamicSharedMemorySize, GEMM_SMEM);
    cudaFuncSetAttribute(gemm_mma<1>,
                         cudaFuncAttributeMaxDynamicSharedMemorySize, GEMM_SMEM);

    int tbl_threads = T * RM + BB * NBIAS;
    tables_kernel<<<(tbl_threads + 255) / 256, 256>>>(coords, W_rope, W_fb, bcos, bsin);
    gemm_mma<0><<<dim3(3 * C / 128, BB * T / 64), 128, GEMM_SMEM>>>(
        x, W_attn, b_attn, nullptr, nullptr);
    attn_kernel<<<dim3(T / 64, H, BB), 128, ATTN_SMEM>>>();
    gemm_mma<1><<<dim3(C / 128, BB * T / 64), 128, GEMM_SMEM>>>(
        nullptr, W_proj, b_proj, x, out);
}